// round 15
// baseline (speedup 1.0000x reference)
#include <cuda_runtime.h>
#include <cuda_fp16.h>
#include <cstdint>

#define SPX 3136      // 56*56
#define BATCH 8
#define DIM 256
#define DIM2 512
#define ROWS_TOT (BATCH * SPX)   // 25088 = 196 * 128

// ---------------- scratch (static __device__, allocation-free) ----------------
__device__ __half g_xTh[(size_t)ROWS_TOT * DIM];     // fp16(x^T) [B*S, 256]
__device__ __half g_cath[(size_t)ROWS_TOT * DIM2];   // [B*S, 512] = [h | xj]
__device__ __half g_gh[(size_t)ROWS_TOT * DIM2];     // gelu out [B*S, 512]
__device__ float g_part[(size_t)ROWS_TOT * DIM];     // fc2 split-K fp32 partials
__device__ __half g_w1h[(size_t)DIM * DIM];          // fp16(w1) [256,256]
__device__ __half g_wgh[(size_t)DIM2 * DIM2];        // fp16(wg) [512,512]
__device__ __half g_w2h[(size_t)DIM * DIM2];         // fp16(w2) [256,512]
// packed two-smallest {m1,m2}:
__device__ float2 g_cmm[(size_t)BATCH * 56 * 2 * DIM];      // col mins merged: (b, x, parity, c)
__device__ float2 g_rmp[(size_t)BATCH * 56 * 2 * 2 * DIM];  // row: (b, y, x-half, parity, c)
// flags: [0,784) gemm2 tile-done, [784,1176) fc2 split-K partial-done
__device__ int g_flags[1176];
__device__ float g_sc1[DIM], g_sh1[DIM];
__device__ float g_scg[DIM2], g_shg[DIM2];
__device__ float g_sc2[DIM], g_sh2[DIM];

// ---------------- PTX helpers (sm_80-generic only) ----------------
__device__ __forceinline__ uint32_t smem_u32(const void* p) {
    uint32_t a;
    asm("{ .reg .u64 t; cvta.to.shared.u64 t, %1; cvt.u32.u64 %0, t; }" : "=r"(a) : "l"(p));
    return a;
}
#define CP_ASYNC16(sm, gm) \
    asm volatile("cp.async.cg.shared.global [%0], [%1], 16;" :: "r"(sm), "l"(gm) : "memory")
#define CP_COMMIT() asm volatile("cp.async.commit_group;" ::: "memory")
#define CP_WAIT1() asm volatile("cp.async.wait_group 1;" ::: "memory")
#define CP_WAIT0() asm volatile("cp.async.wait_group 0;" ::: "memory")
#define LDSM_X4(r0, r1, r2, r3, addr)                                        \
    asm volatile("ldmatrix.sync.aligned.m8n8.x4.shared.b16 {%0,%1,%2,%3}, [%4];" \
                 : "=r"(r0), "=r"(r1), "=r"(r2), "=r"(r3) : "r"(addr))

__device__ __forceinline__ void mma_fp16(float* d, const uint32_t* a, const uint32_t* b) {
    asm volatile(
        "mma.sync.aligned.m16n8k16.row.col.f32.f16.f16.f32 "
        "{%0,%1,%2,%3}, {%4,%5,%6,%7}, {%8,%9}, {%0,%1,%2,%3};"
        : "+f"(d[0]), "+f"(d[1]), "+f"(d[2]), "+f"(d[3])
        : "r"(a[0]), "r"(a[1]), "r"(a[2]), "r"(a[3]), "r"(b[0]), "r"(b[1]));
}

// two-smallest update / merge (exact)
__device__ __forceinline__ void ts_upd(float& m1, float& m2, float v) {
    if (v < m1) { m2 = m1; m1 = v; } else if (v < m2) { m2 = v; }
}
__device__ __forceinline__ float2 ts_merge2(float2 a, float2 b) {
    float2 r;
    r.x = fminf(a.x, b.x);
    r.y = fminf(fmaxf(a.x, b.x), fminf(a.y, b.y));
    return r;
}

// ---------------- fused transpose_in + prep + weight packing + flag reset ----------------
__global__ void __launch_bounds__(256) fused_prep(const float* __restrict__ x,
                          const float* __restrict__ w1, const float* __restrict__ wg,
                          const float* __restrict__ w2,
                          const float* __restrict__ b1, const float* __restrict__ g1,
                          const float* __restrict__ be1, const float* __restrict__ m1,
                          const float* __restrict__ v1,
                          const float* __restrict__ bg, const float* __restrict__ gg,
                          const float* __restrict__ beg, const float* __restrict__ mg,
                          const float* __restrict__ vg,
                          const float* __restrict__ b2, const float* __restrict__ g2,
                          const float* __restrict__ be2, const float* __restrict__ m2,
                          const float* __restrict__ v2) {
    int blk = blockIdx.x;
    if (blk < 6272) {
        __shared__ float t[32][33];
        int tx = threadIdx.x & 31, ty = threadIdx.x >> 5;
        int s0 = (blk % 98) * 32, c0 = ((blk / 98) & 7) * 32, b = blk / 784;
        const float* xp = x + ((size_t)b * DIM + c0) * SPX + s0;
        for (int i = ty; i < 32; i += 8) t[i][tx] = xp[(size_t)i * SPX + tx];
        __syncthreads();
        __half* op = g_xTh + ((size_t)(b * SPX + s0)) * DIM + c0;
        for (int i = ty; i < 32; i += 8)
            op[(size_t)i * DIM + tx] = __float2half_rn(t[tx][i]);
        return;
    }
    if (blk < 6720) {
        int pb = blk - 6272;
        int idx = pb * 256 + threadIdx.x;  // float4 index
        const float4* src;
        __half* dst;
        if (pb < 64) { src = (const float4*)w1; dst = g_w1h; }
        else if (pb < 320) { src = (const float4*)wg; dst = g_wgh; idx -= 16384; }
        else { src = (const float4*)w2; dst = g_w2h; idx -= 81920; }
        float4 f = src[idx];
        *(__half2*)(dst + (size_t)idx * 4) = __floats2half2_rn(f.x, f.y);
        *(__half2*)(dst + (size_t)idx * 4 + 2) = __floats2half2_rn(f.z, f.w);
        return;
    }
    int i = threadIdx.x;
    {
        float s = g1[i] / sqrtf(v1[i] + 1e-5f);
        g_sc1[i] = s; g_sh1[i] = (b1[i] - m1[i]) * s + be1[i];
        float s2 = g2[i] / sqrtf(v2[i] + 1e-5f);
        g_sc2[i] = s2; g_sh2[i] = (b2[i] - m2[i]) * s2 + be2[i];
    }
#pragma unroll
    for (int r = 0; r < 2; r++) {
        int j = i + r * 256;
        float sg = gg[j] / sqrtf(vg[j] + 1e-5f);
        g_scg[j] = sg; g_shg[j] = (bg[j] - mg[j]) * sg + beg[j];
    }
    for (int j = i; j < 1176; j += 256) g_flags[j] = 0;
}

// ---------------- MRConv4d pass 1: col (full) + row (halves), 4-way tracker ILP ----------------
__global__ void __launch_bounds__(256) minpass_kernel() {
    int b = blockIdx.y, c = threadIdx.x;
    float m1[4], m2[4];
#pragma unroll
    for (int q = 0; q < 4; q++) { m1[q] = 1e30f; m2[q] = 1e30f; }
    if (blockIdx.z == 0) {
        int x = blockIdx.x;
        const __half* base = g_cath + ((size_t)(b * SPX + x)) * DIM2 + c;
        for (int j = 0; j < 14; j++) {
            float v[4];
#pragma unroll
            for (int q = 0; q < 4; q++)
                v[q] = __half2float(__ldg(&base[(size_t)((4 * j + q) * 56) * DIM2]));
#pragma unroll
            for (int q = 0; q < 4; q++) ts_upd(m1[q], m2[q], v[q]);
        }
        float2 e = ts_merge2(make_float2(m1[0], m2[0]), make_float2(m1[2], m2[2]));
        float2 o = ts_merge2(make_float2(m1[1], m2[1]), make_float2(m1[3], m2[3]));
        size_t ofs = (((size_t)(b * 56 + x)) * 2) * DIM + c;
        g_cmm[ofs] = e;
        g_cmm[ofs + DIM] = o;
    } else {
        int y = blockIdx.x, h = blockIdx.z - 1;
        const __half* base = g_cath + ((size_t)(b * SPX + y * 56 + h * 28)) * DIM2 + c;
        for (int j = 0; j < 7; j++) {
            float v[4];
#pragma unroll
            for (int q = 0; q < 4; q++)
                v[q] = __half2float(__ldg(&base[(size_t)(4 * j + q) * DIM2]));
#pragma unroll
            for (int q = 0; q < 4; q++) ts_upd(m1[q], m2[q], v[q]);
        }
        float2 e = ts_merge2(make_float2(m1[0], m2[0]), make_float2(m1[2], m2[2]));
        float2 o = ts_merge2(make_float2(m1[1], m2[1]), make_float2(m1[3], m2[3]));
        size_t ofs = (((size_t)(b * 56 + y) * 2 + h) * 2) * DIM + c;
        g_rmp[ofs] = e;
        g_rmp[ofs + DIM] = o;
    }
}

// ---------------- MRConv4d pass 2: combine -> xj (front-batched loads) ----------------
__global__ void __launch_bounds__(256) combine_kernel() {
    int y = blockIdx.x, b = blockIdx.y, xq = blockIdx.z, c = threadIdx.x;
    float2 r[2];
    {
        size_t o0 = (((size_t)(b * 56 + y) * 2 + 0) * 2) * DIM + c;
        size_t o1 = o0 + 2 * DIM;
#pragma unroll
        for (int p = 0; p < 2; p++)
            r[p] = ts_merge2(g_rmp[o0 + p * DIM], g_rmp[o1 + p * DIM]);
    }
    int py = y & 1;
    const int x0 = xq * 14;
    const __half* hb = g_cath + ((size_t)(b * SPX + y * 56 + x0)) * DIM2 + c;
    __half* ob = g_cath + ((size_t)(b * SPX + y * 56 + x0)) * DIM2 + DIM + c;
    const float2* cmb = g_cmm + (((size_t)(b * 56 + x0)) * 2 + py) * DIM + c;

    __half hv[14];
    float2 cmv[14];
#pragma unroll
    for (int i = 0; i < 14; i++) hv[i] = __ldg(&hb[(size_t)i * DIM2]);
#pragma unroll
    for (int i = 0; i < 14; i++) cmv[i] = __ldg(&cmb[(size_t)i * 2 * DIM]);

#pragma unroll
    for (int i = 0; i < 14; i++) {
        float v = __half2float(hv[i]);
        float ec = (v == cmv[i].x) ? cmv[i].y : cmv[i].x;
        float2 rr = r[i & 1];
        float er = (v == rr.x) ? rr.y : rr.x;
        ob[(size_t)i * DIM2] = __float2half_rn(fmaxf(0.0f, v - fminf(ec, er)));
    }
}

// ---------------- GEMM tile body (device function, fully templated) ----------------
// CTA 128x128, 8 warps (2m x 4n) of 64x32, BK=64, 2-stage cp.async.
// MODE 0: BN -> fp16, row stride 512
// MODE 1: BN + exact GELU -> fp16, row stride 512
// MODE 2: split-K fc2. bz = k-half. 0: raw fp32 partial + flag; 1: wait, add,
//         BN + residual + transposed fp32 store.
#define GSMEM 66560
template <int MODE, int KSTRIDE, int KLEN>
__device__ __forceinline__ void gemm_body(
    int bx, int by, int bz, char* smem,
    const __half* __restrict__ Ag, const __half* __restrict__ Wg,
    void* __restrict__ dstv, const float* __restrict__ xres,
    float* __restrict__ partial, int* __restrict__ flags,
    const float* __restrict__ scale, const float* __restrict__ shift) {
    __shared__ float s_scale[128], s_shift[128];
    const int tid = threadIdx.x, lane = tid & 31, wid = tid >> 5;
    const int warp_m = wid >> 2, warp_n = wid & 3;
    const int r0 = bx * 128, n0 = by * 128;
    const int koff = (MODE == 2) ? bz * KLEN : 0;
    const uint32_t sb = smem_u32(smem);
    if (tid < 128) { s_scale[tid] = scale[n0 + tid]; s_shift[tid] = shift[n0 + tid]; }

    uint32_t loff[4];
    size_t aoff[4], boff[4];
#pragma unroll
    for (int i = 0; i < 4; i++) {
        int idx = tid + i * 256;
        int row = idx >> 3, c = idx & 7;
        loff[i] = row * 128 + ((c ^ (row & 7)) << 4);
        aoff[i] = (size_t)(r0 + row) * KSTRIDE + koff + c * 8;
        boff[i] = (size_t)(n0 + row) * KSTRIDE + koff + c * 8;
    }

    const int rowA[4] = {warp_m * 64 + 0 * 16 + (lane & 7) + ((lane >> 3) & 1) * 8,
                         warp_m * 64 + 1 * 16 + (lane & 7) + ((lane >> 3) & 1) * 8,
                         warp_m * 64 + 2 * 16 + (lane & 7) + ((lane >> 3) & 1) * 8,
                         warp_m * 64 + 3 * 16 + (lane & 7) + ((lane >> 3) & 1) * 8};
    const int kcA = lane >> 4;
    const int rowB[2] = {warp_n * 32 + 0 * 16 + (lane & 7) + ((lane >> 4) & 1) * 8,
                         warp_n * 32 + 1 * 16 + (lane & 7) + ((lane >> 4) & 1) * 8};
    const int kcB = (lane >> 3) & 1;

    float acc[4][4][4];
#pragma unroll
    for (int a = 0; a < 4; a++)
#pragma unroll
        for (int b = 0; b < 4; b++)
#pragma unroll
            for (int i = 0; i < 4; i++) acc[a][b][i] = 0.0f;

    constexpr int NS = KLEN >> 6;

#pragma unroll
    for (int i = 0; i < 4; i++) {
        CP_ASYNC16(sb + loff[i], Ag + aoff[i]);
        CP_ASYNC16(sb + 16384 + loff[i], Wg + boff[i]);
    }
    CP_COMMIT();

#pragma unroll
    for (int s = 0; s < NS; s++) {
        const uint32_t aBase = sb + (s & 1) * 32768;
        const uint32_t bBase = aBase + 16384;
        if (s + 1 < NS) {
            const uint32_t nb = sb + ((s + 1) & 1) * 32768;
            const size_t kadd = (size_t)(s + 1) * 64;
#pragma unroll
            for (int i = 0; i < 4; i++) {
                CP_ASYNC16(nb + loff[i], Ag + aoff[i] + kadd);
                CP_ASYNC16(nb + 16384 + loff[i], Wg + boff[i] + kadd);
            }
            CP_COMMIT();
            CP_WAIT1();
        } else {
            CP_WAIT0();
        }
        __syncthreads();

#pragma unroll
        for (int kk = 0; kk < 4; kk++) {
            uint32_t af[4][4];
#pragma unroll
            for (int mf = 0; mf < 4; mf++) {
                uint32_t addr = aBase + rowA[mf] * 128 +
                                (((kk * 2 + kcA) ^ (rowA[mf] & 7)) << 4);
                LDSM_X4(af[mf][0], af[mf][1], af[mf][2], af[mf][3], addr);
            }
            uint32_t bf[2][4];
#pragma unroll
            for (int nb2 = 0; nb2 < 2; nb2++) {
                uint32_t addr = bBase + rowB[nb2] * 128 +
                                (((kk * 2 + kcB) ^ (rowB[nb2] & 7)) << 4);
                LDSM_X4(bf[nb2][0], bf[nb2][1], bf[nb2][2], bf[nb2][3], addr);
            }
#pragma unroll
            for (int mf = 0; mf < 4; mf++)
#pragma unroll
                for (int nf = 0; nf < 4; nf++)
                    mma_fp16(acc[mf][nf], af[mf], &bf[nf >> 1][(nf & 1) * 2]);
        }
        __syncthreads();
    }

    // ---------------- epilogue ----------------
    if (MODE == 2) {
        const int tileid = bx + by * 196;
        if (bz == 0) {
#pragma unroll
            for (int mf = 0; mf < 4; mf++)
#pragma unroll
                for (int nf = 0; nf < 4; nf++)
#pragma unroll
                    for (int half = 0; half < 2; half++) {
                        int grow = r0 + warp_m * 64 + mf * 16 + (lane >> 2) + half * 8;
                        int lcol = warp_n * 32 + nf * 8 + (lane & 3) * 2;
                        *(float2*)(partial + (size_t)grow * 256 + n0 + lcol) =
                            make_float2(acc[mf][nf][half * 2 + 0], acc[mf][nf][half * 2 + 1]);
                    }
            __threadfence();
            __syncthreads();
            if (tid == 0) atomicExch(&flags[tileid], 1);
            return;
        }
        if (tid == 0) {
            while (atomicAdd(&flags[tileid], 0) == 0) {}
        }
        __syncthreads();
        __threadfence();
#pragma unroll
        for (int mf = 0; mf < 4; mf++)
#pragma unroll
            for (int nf = 0; nf < 4; nf++)
#pragma unroll
                for (int half = 0; half < 2; half++) {
                    int grow = r0 + warp_m * 64 + mf * 16 + (lane >> 2) + half * 8;
                    int lcol = warp_n * 32 + nf * 8 + (lane & 3) * 2;
                    float2 p = *(const float2*)(partial + (size_t)grow * 256 + n0 + lcol);
                    acc[mf][nf][half * 2 + 0] += p.x;
                    acc[mf][nf][half * 2 + 1] += p.y;
                }
        __syncthreads();
        float* stg = (float*)smem;  // 128 x 129 fp32 staging
#pragma unroll
        for (int mf = 0; mf < 4; mf++)
#pragma unroll
            for (int nf = 0; nf < 4; nf++)
#pragma unroll
                for (int half = 0; half < 2; half++) {
                    int rl = warp_m * 64 + mf * 16 + (lane >> 2) + half * 8;
                    int cl = warp_n * 32 + nf * 8 + (lane & 3) * 2;
                    stg[rl * 129 + cl] = fmaf(acc[mf][nf][half * 2 + 0], s_scale[cl], s_shift[cl]);
                    stg[rl * 129 + cl + 1] =
                        fmaf(acc[mf][nf][half * 2 + 1], s_scale[cl + 1], s_shift[cl + 1]);
                }
        __syncthreads();
        float* out = (float*)dstv;
#pragma unroll
        for (int cc = 0; cc < 16; cc++) {
            int c = wid * 16 + cc;
#pragma unroll
            for (int j = 0; j < 4; j++) {
                int i = lane + 32 * j;
                int r = r0 + i;
                int b = r / SPX;
                size_t o = ((size_t)(b * DIM + n0 + c)) * SPX + (r - b * SPX);
                out[o] = stg[i * 129 + c] + xres[o];
            }
        }
        return;
    }

    const int mw = r0 + warp_m * 64;
    const int nw = warp_n * 32;
    __half* dp_base = (__half*)dstv;
#pragma unroll
    for (int mf = 0; mf < 4; mf++) {
#pragma unroll
        for (int nf = 0; nf < 4; nf++) {
#pragma unroll
            for (int half = 0; half < 2; half++) {
                int grow = mw + mf * 16 + (lane >> 2) + half * 8;
                int lcol = nw + nf * 8 + (lane & 3) * 2;
                float v0 = fmaf(acc[mf][nf][half * 2 + 0], s_scale[lcol], s_shift[lcol]);
                float v1 = fmaf(acc[mf][nf][half * 2 + 1], s_scale[lcol + 1], s_shift[lcol + 1]);
                if (MODE == 1) {
                    v0 = 0.5f * v0 * (1.0f + erff(v0 * 0.70710678118654752f));
                    v1 = 0.5f * v1 * (1.0f + erff(v1 * 0.70710678118654752f));
                }
                __half2 hp;
                hp.x = __float2half_rn(v0);
                hp.y = __float2half_rn(v1);
                *(__half2*)(dp_base + (size_t)grow * DIM2 + n0 + lcol) = hp;
            }
        }
    }
}

// ---------------- fc1 kernel (standalone) ----------------
__global__ void __launch_bounds__(256, 2)
fc1_kernel(const __half* __restrict__ Ag, const __half* __restrict__ Wg,
           void* __restrict__ dstv, const float* __restrict__ scale,
           const float* __restrict__ shift) {
    extern __shared__ __align__(1024) char smem[];
    gemm_body<0, 256, 256>(blockIdx.x, blockIdx.y, 0, smem, Ag, Wg, dstv,
                           nullptr, nullptr, nullptr, scale, shift);
}

// ---------------- fused gemm2 + fc2: one launch, flag-chained tiles ----------------
// bids [0,784): gemm2 tile (r0i = bid%196, n0i = bid/196). Writes gh, publishes flag.
// bids [784,1568): fc2 tile. t = bid-784; z = t/392; u = t%392; r0i = u%196, n0i = u/392? 
//   (u: r0i = u%196, n0i = u/196). Waits on gemm2 flags {r0i + 392z, r0i + 196 + 392z}.
__global__ void __launch_bounds__(256, 2)
fused_g2fc2(const __half* __restrict__ cath, const __half* __restrict__ wgh,
            __half* __restrict__ gh, const __half* __restrict__ w2h,
            float* __restrict__ out, const float* __restrict__ xres,
            float* __restrict__ partial, int* __restrict__ flags,
            const float* __restrict__ scg, const float* __restrict__ shg,
            const float* __restrict__ sc2, const float* __restrict__ sh2) {
    extern __shared__ __align__(1024) char smem[];
    int bid = blockIdx.x;
    if (bid < 784) {
        int r0i = bid % 196, n0i = bid / 196;
        gemm_body<1, 512, 512>(r0i, n0i, 0, smem, cath, wgh, gh,
                               nullptr, nullptr, nullptr, scg, shg);
        __threadfence();
        __syncthreads();
        if (threadIdx.x == 0) atomicExch(&flags[bid], 1);
        return;
    }
    int t = bid - 784;
    int z = t / 392;
    int u = t - z * 392;
    int r0i = u % 196, n0i = u / 196;
    // wait for the two gemm2 producer tiles covering gh[r0 rows, 256z .. 256z+255]
    if (threadIdx.x == 0) {
        int p0 = r0i + 392 * z;
        int p1 = p0 + 196;
        while (atomicAdd(&flags[p0], 0) == 0) {}
        while (atomicAdd(&flags[p1], 0) == 0) {}
    }
    __syncthreads();
    __threadfence();
    gemm_body<2, 512, 256>(r0i, n0i, z, smem, gh, w2h, out,
                           xres, partial, flags + 784, sc2, sh2);
}

// ---------------------------------------------------------------------------
extern "C" void kernel_launch(void* const* d_in, const int* in_sizes, int n_in,
                              void* d_out, int out_size) {
    const float* x   = (const float*)d_in[0];
    const float* w1  = (const float*)d_in[1];
    const float* b1  = (const float*)d_in[2];
    const float* g1  = (const float*)d_in[3];
    const float* be1 = (const float*)d_in[4];
    const float* m1  = (const float*)d_in[5];
    const float* v1  = (const float*)d_in[6];
    const float* wg  = (const float*)d_in[7];
    const float* bg  = (const float*)d_in[8];
    const float* gg  = (const float*)d_in[9];
    const float* beg = (const float*)d_in[10];
    const float* mg  = (const float*)d_in[11];
    const float* vg  = (const float*)d_in[12];
    const float* w2  = (const float*)d_in[13];
    const float* b2  = (const float*)d_in[14];
    const float* g2  = (const float*)d_in[15];
    const float* be2 = (const float*)d_in[16];
    const float* m2  = (const float*)d_in[17];
    const float* v2  = (const float*)d_in[18];

    __half *xTh, *cath, *gh, *w1h, *wgh, *w2h;
    float *part, *sc1, *sh1, *scg, *shg, *sc2, *sh2;
    int* flags;
    cudaGetSymbolAddress((void**)&xTh, g_xTh);
    cudaGetSymbolAddress((void**)&cath, g_cath);
    cudaGetSymbolAddress((void**)&gh, g_gh);
    cudaGetSymbolAddress((void**)&part, g_part);
    cudaGetSymbolAddress((void**)&w1h, g_w1h);
    cudaGetSymbolAddress((void**)&wgh, g_wgh);
    cudaGetSymbolAddress((void**)&w2h, g_w2h);
    cudaGetSymbolAddress((void**)&sc1, g_sc1);
    cudaGetSymbolAddress((void**)&sh1, g_sh1);
    cudaGetSymbolAddress((void**)&scg, g_scg);
    cudaGetSymbolAddress((void**)&shg, g_shg);
    cudaGetSymbolAddress((void**)&sc2, g_sc2);
    cudaGetSymbolAddress((void**)&sh2, g_sh2);
    cudaGetSymbolAddress((void**)&flags, g_flags);

    cudaFuncSetAttribute(fc1_kernel, cudaFuncAttributeMaxDynamicSharedMemorySize, GSMEM);
    cudaFuncSetAttribute(fused_g2fc2, cudaFuncAttributeMaxDynamicSharedMemorySize, GSMEM);

    // transpose + weight pack + BN fold + flag reset (one launch, concurrent blocks)
    fused_prep<<<6721, 256>>>(x, w1, wg, w2, b1, g1, be1, m1, v1,
                              bg, gg, beg, mg, vg, b2, g2, be2, m2, v2);

    // fc1: cat[:, 0:256] = fp16(BN(x @ w1^T))
    fc1_kernel<<<dim3(196, 2), 256, GSMEM>>>(xTh, w1h, cath, sc1, sh1);
    // MRConv4d -> cat[:, 256:512]
    minpass_kernel<<<dim3(56, 8, 3), 256>>>();
    combine_kernel<<<dim3(56, 8, 4), 256>>>();
    // fused: g = fp16(GELU(BN(cat @ wg^T))), then out = BN(g @ w2^T)^T + x
    fused_g2fc2<<<1568, 256, GSMEM>>>(cath, wgh, gh, w2h, (float*)d_out, x,
                                      part, flags, scg, shg, sc2, sh2);
}

// round 16
// speedup vs baseline: 1.0010x; 1.0010x over previous
#include <cuda_runtime.h>
#include <cuda_fp16.h>
#include <cstdint>

#define SPX 3136      // 56*56
#define BATCH 8
#define DIM 256
#define DIM2 512
#define ROWS_TOT (BATCH * SPX)   // 25088 = 196 * 128

// ---------------- scratch (static __device__, allocation-free) ----------------
__device__ __half g_xTh[(size_t)ROWS_TOT * DIM];     // fp16(x^T) [B*S, 256]
__device__ __half g_cath[(size_t)ROWS_TOT * DIM2];   // [B*S, 512] = [h | xj]; reused as fp32
                                                     // split-K partial scratch for fc2
__device__ __half g_gh[(size_t)ROWS_TOT * DIM2];     // gelu out [B*S, 512]
__device__ __half g_w1h[(size_t)DIM * DIM];          // fp16(w1) [256,256]
__device__ __half g_wgh[(size_t)DIM2 * DIM2];        // fp16(wg) [512,512]
__device__ __half g_w2h[(size_t)DIM * DIM2];         // fp16(w2) [256,512]
// packed two-smallest {m1,m2}:
__device__ float2 g_cmm[(size_t)BATCH * 56 * 2 * DIM];      // col mins merged: (b, x, parity, c)
__device__ float2 g_rmp[(size_t)BATCH * 56 * 2 * 2 * DIM];  // row: (b, y, x-half, parity, c)
__device__ int g_flags[392];                          // fc2 split-K tile flags
__device__ float g_sc1[DIM], g_sh1[DIM];
__device__ float g_scg[DIM2], g_shg[DIM2];
__device__ float g_sc2[DIM], g_sh2[DIM];

// ---------------- PTX helpers (sm_80-generic only) ----------------
__device__ __forceinline__ uint32_t smem_u32(const void* p) {
    uint32_t a;
    asm("{ .reg .u64 t; cvta.to.shared.u64 t, %1; cvt.u32.u64 %0, t; }" : "=r"(a) : "l"(p));
    return a;
}
#define CP_ASYNC16(sm, gm) \
    asm volatile("cp.async.cg.shared.global [%0], [%1], 16;" :: "r"(sm), "l"(gm) : "memory")
#define CP_COMMIT() asm volatile("cp.async.commit_group;" ::: "memory")
#define CP_WAIT1() asm volatile("cp.async.wait_group 1;" ::: "memory")
#define CP_WAIT0() asm volatile("cp.async.wait_group 0;" ::: "memory")
#define LDSM_X4(r0, r1, r2, r3, addr)                                        \
    asm volatile("ldmatrix.sync.aligned.m8n8.x4.shared.b16 {%0,%1,%2,%3}, [%4];" \
                 : "=r"(r0), "=r"(r1), "=r"(r2), "=r"(r3) : "r"(addr))

__device__ __forceinline__ void mma_fp16(float* d, const uint32_t* a, const uint32_t* b) {
    asm volatile(
        "mma.sync.aligned.m16n8k16.row.col.f32.f16.f16.f32 "
        "{%0,%1,%2,%3}, {%4,%5,%6,%7}, {%8,%9}, {%0,%1,%2,%3};"
        : "+f"(d[0]), "+f"(d[1]), "+f"(d[2]), "+f"(d[3])
        : "r"(a[0]), "r"(a[1]), "r"(a[2]), "r"(a[3]), "r"(b[0]), "r"(b[1]));
}

// two-smallest update / merge (exact)
__device__ __forceinline__ void ts_upd(float& m1, float& m2, float v) {
    if (v < m1) { m2 = m1; m1 = v; } else if (v < m2) { m2 = v; }
}
__device__ __forceinline__ float2 ts_merge2(float2 a, float2 b) {
    float2 r;
    r.x = fminf(a.x, b.x);
    r.y = fminf(fmaxf(a.x, b.x), fminf(a.y, b.y));
    return r;
}

// ---------------- fused transpose_in + prep + weight packing + flag reset ----------------
__global__ void __launch_bounds__(256) fused_prep(const float* __restrict__ x,
                          const float* __restrict__ w1, const float* __restrict__ wg,
                          const float* __restrict__ w2,
                          const float* __restrict__ b1, const float* __restrict__ g1,
                          const float* __restrict__ be1, const float* __restrict__ m1,
                          const float* __restrict__ v1,
                          const float* __restrict__ bg, const float* __restrict__ gg,
                          const float* __restrict__ beg, const float* __restrict__ mg,
                          const float* __restrict__ vg,
                          const float* __restrict__ b2, const float* __restrict__ g2,
                          const float* __restrict__ be2, const float* __restrict__ m2,
                          const float* __restrict__ v2) {
    int blk = blockIdx.x;
    if (blk < 6272) {
        __shared__ float t[32][33];
        int tx = threadIdx.x & 31, ty = threadIdx.x >> 5;
        int s0 = (blk % 98) * 32, c0 = ((blk / 98) & 7) * 32, b = blk / 784;
        const float* xp = x + ((size_t)b * DIM + c0) * SPX + s0;
        for (int i = ty; i < 32; i += 8) t[i][tx] = xp[(size_t)i * SPX + tx];
        __syncthreads();
        __half* op = g_xTh + ((size_t)(b * SPX + s0)) * DIM + c0;
        for (int i = ty; i < 32; i += 8)
            op[(size_t)i * DIM + tx] = __float2half_rn(t[tx][i]);
        return;
    }
    if (blk < 6720) {
        int pb = blk - 6272;
        int idx = pb * 256 + threadIdx.x;  // float4 index
        const float4* src;
        __half* dst;
        if (pb < 64) { src = (const float4*)w1; dst = g_w1h; }
        else if (pb < 320) { src = (const float4*)wg; dst = g_wgh; idx -= 16384; }
        else { src = (const float4*)w2; dst = g_w2h; idx -= 81920; }
        float4 f = src[idx];
        *(__half2*)(dst + (size_t)idx * 4) = __floats2half2_rn(f.x, f.y);
        *(__half2*)(dst + (size_t)idx * 4 + 2) = __floats2half2_rn(f.z, f.w);
        return;
    }
    int i = threadIdx.x;
    {
        float s = g1[i] / sqrtf(v1[i] + 1e-5f);
        g_sc1[i] = s; g_sh1[i] = (b1[i] - m1[i]) * s + be1[i];
        float s2 = g2[i] / sqrtf(v2[i] + 1e-5f);
        g_sc2[i] = s2; g_sh2[i] = (b2[i] - m2[i]) * s2 + be2[i];
    }
#pragma unroll
    for (int r = 0; r < 2; r++) {
        int j = i + r * 256;
        float sg = gg[j] / sqrtf(vg[j] + 1e-5f);
        g_scg[j] = sg; g_shg[j] = (bg[j] - mg[j]) * sg + beg[j];
    }
    if (i < 256) g_flags[i] = 0;
    if (i + 256 < 392) g_flags[i + 256] = 0;
}

// ---------------- MRConv4d pass 1: col (full) + row (halves), 4-way tracker ILP ----------------
// grid (56, 8, 3): z=0 -> full column pass (x = bx) writing merged g_cmm directly
//                  z=1,2 -> row pass (y = bx, x-half = z-1) into g_rmp
__global__ void __launch_bounds__(256) minpass_kernel() {
    int b = blockIdx.y, c = threadIdx.x;
    float m1[4], m2[4];
#pragma unroll
    for (int q = 0; q < 4; q++) { m1[q] = 1e30f; m2[q] = 1e30f; }
    if (blockIdx.z == 0) {
        int x = blockIdx.x;
        const __half* base = g_cath + ((size_t)(b * SPX + x)) * DIM2 + c;
        for (int j = 0; j < 14; j++) {
            float v[4];
#pragma unroll
            for (int q = 0; q < 4; q++)
                v[q] = __half2float(__ldg(&base[(size_t)((4 * j + q) * 56) * DIM2]));
#pragma unroll
            for (int q = 0; q < 4; q++) ts_upd(m1[q], m2[q], v[q]);
        }
        // merge mod-4 classes {0,2} -> even parity, {1,3} -> odd (exact)
        float2 e = ts_merge2(make_float2(m1[0], m2[0]), make_float2(m1[2], m2[2]));
        float2 o = ts_merge2(make_float2(m1[1], m2[1]), make_float2(m1[3], m2[3]));
        size_t ofs = (((size_t)(b * 56 + x)) * 2) * DIM + c;
        g_cmm[ofs] = e;
        g_cmm[ofs + DIM] = o;
    } else {
        int y = blockIdx.x, h = blockIdx.z - 1;
        const __half* base = g_cath + ((size_t)(b * SPX + y * 56 + h * 28)) * DIM2 + c;
        for (int j = 0; j < 7; j++) {
            float v[4];
#pragma unroll
            for (int q = 0; q < 4; q++)
                v[q] = __half2float(__ldg(&base[(size_t)(4 * j + q) * DIM2]));
#pragma unroll
            for (int q = 0; q < 4; q++) ts_upd(m1[q], m2[q], v[q]);
        }
        float2 e = ts_merge2(make_float2(m1[0], m2[0]), make_float2(m1[2], m2[2]));
        float2 o = ts_merge2(make_float2(m1[1], m2[1]), make_float2(m1[3], m2[3]));
        size_t ofs = (((size_t)(b * 56 + y) * 2 + h) * 2) * DIM + c;
        g_rmp[ofs] = e;
        g_rmp[ofs + DIM] = o;
    }
}

// ---------------- MRConv4d pass 2: combine -> xj (4-y groups, cm amortized) ----------------
// grid (14 y-group, 8 b, 4 x-quarter), 256 threads; block covers 4 y x 14 x.
// cm (both parities, 14 x) loaded ONCE per block; per-y: rm (4 float2) + 14 h loads.
__global__ void __launch_bounds__(256) combine_kernel() {
    int yg = blockIdx.x, b = blockIdx.y, xq = blockIdx.z, c = threadIdx.x;
    const int y0 = yg * 4;
    const int x0 = xq * 14;

    // column mins for both parities, all 14 x's (reused across 4 y's)
    float2 cmv[2][14];
    const float2* cmb = g_cmm + (((size_t)(b * 56 + x0)) * 2) * DIM + c;
#pragma unroll
    for (int i = 0; i < 14; i++) {
        cmv[0][i] = __ldg(&cmb[(size_t)(i * 2 + 0) * DIM]);
        cmv[1][i] = __ldg(&cmb[(size_t)(i * 2 + 1) * DIM]);
    }

#pragma unroll
    for (int yy = 0; yy < 4; yy++) {
        int y = y0 + yy;
        int py = y & 1;
        // merged row mins for this (b, y): parity 0 and 1
        float2 r[2];
        size_t o0 = (((size_t)(b * 56 + y) * 2 + 0) * 2) * DIM + c;
        size_t o1 = o0 + 2 * DIM;
#pragma unroll
        for (int p = 0; p < 2; p++)
            r[p] = ts_merge2(__ldg(&g_rmp[o0 + p * DIM]), __ldg(&g_rmp[o1 + p * DIM]));

        const __half* hb = g_cath + ((size_t)(b * SPX + y * 56 + x0)) * DIM2 + c;
        __half* ob = g_cath + ((size_t)(b * SPX + y * 56 + x0)) * DIM2 + DIM + c;
        __half hv[14];
#pragma unroll
        for (int i = 0; i < 14; i++) hv[i] = __ldg(&hb[(size_t)i * DIM2]);
#pragma unroll
        for (int i = 0; i < 14; i++) {
            float v = __half2float(hv[i]);
            float2 cm = cmv[py][i];
            float ec = (v == cm.x) ? cm.y : cm.x;
            float2 rr = r[i & 1];  // x0 even -> global parity = i&1
            float er = (v == rr.x) ? rr.y : rr.x;
            ob[(size_t)i * DIM2] = __float2half_rn(fmaxf(0.0f, v - fminf(ec, er)));
        }
    }
}

// ---------------- fp16 mma.sync GEMM ----------------
// CTA 128x128, 8 warps (2m x 4n) of 64x32, BK=64, 256 threads, 2 CTAs/SM, 2-stage.
// MODE 0: BN -> fp16, row stride 512 (fc1)
// MODE 1: BN + exact GELU -> fp16, row stride 512 (gemm2)
// MODE 2: split-K fc2. blockIdx.z = k-half. half 0: raw fp32 partial + flag.
//         half 1: wait flag, add partial, BN + residual + transposed fp32 store.
#define GSMEM 66560
template <int MODE, int KSTRIDE, int KLEN>
__global__ void __launch_bounds__(256, 2)
fp16_gemm(const __half* __restrict__ Ag, const __half* __restrict__ Wg,
          void* __restrict__ dstv, const float* __restrict__ xres,
          float* __restrict__ partial, int* __restrict__ flags,
          const float* __restrict__ scale, const float* __restrict__ shift) {
    extern __shared__ __align__(1024) char smem[];
    __shared__ float s_scale[128], s_shift[128];
    const int tid = threadIdx.x, lane = tid & 31, wid = tid >> 5;
    const int warp_m = wid >> 2, warp_n = wid & 3;
    const int r0 = blockIdx.x * 128, n0 = blockIdx.y * 128;
    const int koff = (MODE == 2) ? (int)blockIdx.z * KLEN : 0;
    const uint32_t sb = smem_u32(smem);
    if (tid < 128) { s_scale[tid] = scale[n0 + tid]; s_shift[tid] = shift[n0 + tid]; }

    uint32_t loff[4];
    size_t aoff[4], boff[4];
#pragma unroll
    for (int i = 0; i < 4; i++) {
        int idx = tid + i * 256;
        int row = idx >> 3, c = idx & 7;
        loff[i] = row * 128 + ((c ^ (row & 7)) << 4);
        aoff[i] = (size_t)(r0 + row) * KSTRIDE + koff + c * 8;
        boff[i] = (size_t)(n0 + row) * KSTRIDE + koff + c * 8;
    }

    const int rowA[4] = {warp_m * 64 + 0 * 16 + (lane & 7) + ((lane >> 3) & 1) * 8,
                         warp_m * 64 + 1 * 16 + (lane & 7) + ((lane >> 3) & 1) * 8,
                         warp_m * 64 + 2 * 16 + (lane & 7) + ((lane >> 3) & 1) * 8,
                         warp_m * 64 + 3 * 16 + (lane & 7) + ((lane >> 3) & 1) * 8};
    const int kcA = lane >> 4;
    const int rowB[2] = {warp_n * 32 + 0 * 16 + (lane & 7) + ((lane >> 4) & 1) * 8,
                         warp_n * 32 + 1 * 16 + (lane & 7) + ((lane >> 4) & 1) * 8};
    const int kcB = (lane >> 3) & 1;

    float acc[4][4][4];
#pragma unroll
    for (int a = 0; a < 4; a++)
#pragma unroll
        for (int b = 0; b < 4; b++)
#pragma unroll
            for (int i = 0; i < 4; i++) acc[a][b][i] = 0.0f;

    constexpr int NS = KLEN >> 6;

    // prologue: stage 0 -> buf 0
#pragma unroll
    for (int i = 0; i < 4; i++) {
        CP_ASYNC16(sb + loff[i], Ag + aoff[i]);
        CP_ASYNC16(sb + 16384 + loff[i], Wg + boff[i]);
    }
    CP_COMMIT();

#pragma unroll
    for (int s = 0; s < NS; s++) {
        const uint32_t aBase = sb + (s & 1) * 32768;
        const uint32_t bBase = aBase + 16384;
        if (s + 1 < NS) {
            const uint32_t nb = sb + ((s + 1) & 1) * 32768;
            const size_t kadd = (size_t)(s + 1) * 64;
#pragma unroll
            for (int i = 0; i < 4; i++) {
                CP_ASYNC16(nb + loff[i], Ag + aoff[i] + kadd);
                CP_ASYNC16(nb + 16384 + loff[i], Wg + boff[i] + kadd);
            }
            CP_COMMIT();
            CP_WAIT1();
        } else {
            CP_WAIT0();
        }
        __syncthreads();

#pragma unroll
        for (int kk = 0; kk < 4; kk++) {
            uint32_t af[4][4];
#pragma unroll
            for (int mf = 0; mf < 4; mf++) {
                uint32_t addr = aBase + rowA[mf] * 128 +
                                (((kk * 2 + kcA) ^ (rowA[mf] & 7)) << 4);
                LDSM_X4(af[mf][0], af[mf][1], af[mf][2], af[mf][3], addr);
            }
            uint32_t bf[2][4];
#pragma unroll
            for (int nb2 = 0; nb2 < 2; nb2++) {
                uint32_t addr = bBase + rowB[nb2] * 128 +
                                (((kk * 2 + kcB) ^ (rowB[nb2] & 7)) << 4);
                LDSM_X4(bf[nb2][0], bf[nb2][1], bf[nb2][2], bf[nb2][3], addr);
            }
#pragma unroll
            for (int mf = 0; mf < 4; mf++)
#pragma unroll
                for (int nf = 0; nf < 4; nf++)
                    mma_fp16(acc[mf][nf], af[mf], &bf[nf >> 1][(nf & 1) * 2]);
        }
        __syncthreads();
    }

    // ---------------- epilogue ----------------
    if (MODE == 2) {
        const int tileid = blockIdx.x + blockIdx.y * 196;
        if (blockIdx.z == 0) {
#pragma unroll
            for (int mf = 0; mf < 4; mf++)
#pragma unroll
                for (int nf = 0; nf < 4; nf++)
#pragma unroll
                    for (int half = 0; half < 2; half++) {
                        int grow = r0 + warp_m * 64 + mf * 16 + (lane >> 2) + half * 8;
                        int lcol = warp_n * 32 + nf * 8 + (lane & 3) * 2;
                        *(float2*)(partial + (size_t)grow * 256 + n0 + lcol) =
                            make_float2(acc[mf][nf][half * 2 + 0], acc[mf][nf][half * 2 + 1]);
                    }
            __threadfence();
            __syncthreads();
            if (tid == 0) atomicExch(&flags[tileid], 1);
            return;
        }
        if (tid == 0) {
            while (atomicAdd(&flags[tileid], 0) == 0) {}
        }
        __syncthreads();
        __threadfence();
#pragma unroll
        for (int mf = 0; mf < 4; mf++)
#pragma unroll
            for (int nf = 0; nf < 4; nf++)
#pragma unroll
                for (int half = 0; half < 2; half++) {
                    int grow = r0 + warp_m * 64 + mf * 16 + (lane >> 2) + half * 8;
                    int lcol = warp_n * 32 + nf * 8 + (lane & 3) * 2;
                    float2 p = *(const float2*)(partial + (size_t)grow * 256 + n0 + lcol);
                    acc[mf][nf][half * 2 + 0] += p.x;
                    acc[mf][nf][half * 2 + 1] += p.y;
                }
        __syncthreads();
        float* stg = (float*)smem;  // 128 x 129 fp32 staging
#pragma unroll
        for (int mf = 0; mf < 4; mf++)
#pragma unroll
            for (int nf = 0; nf < 4; nf++)
#pragma unroll
                for (int half = 0; half < 2; half++) {
                    int rl = warp_m * 64 + mf * 16 + (lane >> 2) + half * 8;
                    int cl = warp_n * 32 + nf * 8 + (lane & 3) * 2;
                    stg[rl * 129 + cl] = fmaf(acc[mf][nf][half * 2 + 0], s_scale[cl], s_shift[cl]);
                    stg[rl * 129 + cl + 1] =
                        fmaf(acc[mf][nf][half * 2 + 1], s_scale[cl + 1], s_shift[cl + 1]);
                }
        __syncthreads();
        float* out = (float*)dstv;
#pragma unroll
        for (int cc = 0; cc < 16; cc++) {
            int c = wid * 16 + cc;
#pragma unroll
            for (int j = 0; j < 4; j++) {
                int i = lane + 32 * j;
                int r = r0 + i;
                int b = r / SPX;
                size_t o = ((size_t)(b * DIM + n0 + c)) * SPX + (r - b * SPX);
                out[o] = stg[i * 129 + c] + xres[o];
            }
        }
        return;
    }

    const int mw = r0 + warp_m * 64;
    const int nw = warp_n * 32;
    __half* dp_base = (__half*)dstv;
#pragma unroll
    for (int mf = 0; mf < 4; mf++) {
#pragma unroll
        for (int nf = 0; nf < 4; nf++) {
#pragma unroll
            for (int half = 0; half < 2; half++) {
                int grow = mw + mf * 16 + (lane >> 2) + half * 8;
                int lcol = nw + nf * 8 + (lane & 3) * 2;
                float v0 = fmaf(acc[mf][nf][half * 2 + 0], s_scale[lcol], s_shift[lcol]);
                float v1 = fmaf(acc[mf][nf][half * 2 + 1], s_scale[lcol + 1], s_shift[lcol + 1]);
                if (MODE == 1) {
                    v0 = 0.5f * v0 * (1.0f + erff(v0 * 0.70710678118654752f));
                    v1 = 0.5f * v1 * (1.0f + erff(v1 * 0.70710678118654752f));
                }
                __half2 hp;
                hp.x = __float2half_rn(v0);
                hp.y = __float2half_rn(v1);
                *(__half2*)(dp_base + (size_t)grow * DIM2 + n0 + lcol) = hp;
            }
        }
    }
}

// ---------------------------------------------------------------------------
extern "C" void kernel_launch(void* const* d_in, const int* in_sizes, int n_in,
                              void* d_out, int out_size) {
    const float* x   = (const float*)d_in[0];
    const float* w1  = (const float*)d_in[1];
    const float* b1  = (const float*)d_in[2];
    const float* g1  = (const float*)d_in[3];
    const float* be1 = (const float*)d_in[4];
    const float* m1  = (const float*)d_in[5];
    const float* v1  = (const float*)d_in[6];
    const float* wg  = (const float*)d_in[7];
    const float* bg  = (const float*)d_in[8];
    const float* gg  = (const float*)d_in[9];
    const float* beg = (const float*)d_in[10];
    const float* mg  = (const float*)d_in[11];
    const float* vg  = (const float*)d_in[12];
    const float* w2  = (const float*)d_in[13];
    const float* b2  = (const float*)d_in[14];
    const float* g2  = (const float*)d_in[15];
    const float* be2 = (const float*)d_in[16];
    const float* m2  = (const float*)d_in[17];
    const float* v2  = (const float*)d_in[18];

    __half *xTh, *cath, *gh, *w1h, *wgh, *w2h;
    float *sc1, *sh1, *scg, *shg, *sc2, *sh2;
    int* flags;
    cudaGetSymbolAddress((void**)&xTh, g_xTh);
    cudaGetSymbolAddress((void**)&cath, g_cath);
    cudaGetSymbolAddress((void**)&gh, g_gh);
    cudaGetSymbolAddress((void**)&w1h, g_w1h);
    cudaGetSymbolAddress((void**)&wgh, g_wgh);
    cudaGetSymbolAddress((void**)&w2h, g_w2h);
    cudaGetSymbolAddress((void**)&sc1, g_sc1);
    cudaGetSymbolAddress((void**)&sh1, g_sh1);
    cudaGetSymbolAddress((void**)&scg, g_scg);
    cudaGetSymbolAddress((void**)&shg, g_shg);
    cudaGetSymbolAddress((void**)&sc2, g_sc2);
    cudaGetSymbolAddress((void**)&sh2, g_sh2);
    cudaGetSymbolAddress((void**)&flags, g_flags);

    cudaFuncSetAttribute(fp16_gemm<0, 256, 256>, cudaFuncAttributeMaxDynamicSharedMemorySize, GSMEM);
    cudaFuncSetAttribute(fp16_gemm<1, 512, 512>, cudaFuncAttributeMaxDynamicSharedMemorySize, GSMEM);
    cudaFuncSetAttribute(fp16_gemm<2, 512, 256>, cudaFuncAttributeMaxDynamicSharedMemorySize, GSMEM);

    // transpose + weight pack + BN fold + flag reset (one launch, concurrent blocks)
    fused_prep<<<6721, 256>>>(x, w1, wg, w2, b1, g1, be1, m1, v1,
                              bg, gg, beg, mg, vg, b2, g2, be2, m2, v2);

    // fc1: cat[:, 0:256] = fp16(BN(x @ w1^T))
    fp16_gemm<0, 256, 256><<<dim3(196, 2), 256, GSMEM>>>(
        xTh, w1h, cath, nullptr, nullptr, nullptr, sc1, sh1);
    // MRConv4d -> cat[:, 256:512]
    minpass_kernel<<<dim3(56, 8, 3), 256>>>();
    combine_kernel<<<dim3(14, 8, 4), 256>>>();
    // g = fp16(GELU(BN(cat @ wg^T)))
    fp16_gemm<1, 512, 512><<<dim3(196, 4), 256, GSMEM>>>(
        cath, wgh, gh, nullptr, nullptr, nullptr, scg, shg);
    // fc2 split-K=2: out[B,256,S] = BN(g @ w2^T)^T + x
    fp16_gemm<2, 512, 256><<<dim3(196, 2, 2), 256, GSMEM>>>(
        gh, w2h, d_out, x, (float*)cath, flags, sc2, sh2);
}

// round 17
// speedup vs baseline: 1.0331x; 1.0321x over previous
#include <cuda_runtime.h>
#include <cuda_fp16.h>
#include <cstdint>

#define SPX 3136      // 56*56
#define BATCH 8
#define DIM 256
#define DIM2 512
#define ROWS_TOT (BATCH * SPX)   // 25088 = 196 * 128

// ---------------- scratch (static __device__, allocation-free) ----------------
__device__ __half g_xTh[(size_t)ROWS_TOT * DIM];     // fp16(x^T) [B*S, 256]
__device__ __half g_cath[(size_t)ROWS_TOT * DIM2];   // [B*S, 512] = [h | xj]
__device__ __half g_gh[(size_t)ROWS_TOT * DIM2];     // gelu out [B*S, 512]
__device__ float g_part[(size_t)ROWS_TOT * DIM];     // fc2 split-K fp32 partials
__device__ __half g_w1h[(size_t)DIM * DIM];          // fp16(w1) [256,256]
__device__ __half g_wgh[(size_t)DIM2 * DIM2];        // fp16(wg) [512,512]
__device__ __half g_w2h[(size_t)DIM * DIM2];         // fp16(w2) [256,512]
// packed two-smallest {m1,m2}:
__device__ float2 g_cmm[(size_t)BATCH * 56 * 2 * DIM];      // col mins merged: (b, x, parity, c)
__device__ float2 g_rmp[(size_t)BATCH * 56 * 2 * 2 * DIM];  // row: (b, y, x-half, parity, c)
// flags: [0,784) gemm2 tile-done, [784,1176) fc2 split-K partial-done
__device__ int g_flags[1176];
__device__ int g_counter;                             // persistent-kernel work counter
__device__ float g_sc1[DIM], g_sh1[DIM];
__device__ float g_scg[DIM2], g_shg[DIM2];
__device__ float g_sc2[DIM], g_sh2[DIM];

// ---------------- PTX helpers (sm_80-generic only) ----------------
__device__ __forceinline__ uint32_t smem_u32(const void* p) {
    uint32_t a;
    asm("{ .reg .u64 t; cvta.to.shared.u64 t, %1; cvt.u32.u64 %0, t; }" : "=r"(a) : "l"(p));
    return a;
}
#define CP_ASYNC16(sm, gm) \
    asm volatile("cp.async.cg.shared.global [%0], [%1], 16;" :: "r"(sm), "l"(gm) : "memory")
#define CP_COMMIT() asm volatile("cp.async.commit_group;" ::: "memory")
#define CP_WAIT1() asm volatile("cp.async.wait_group 1;" ::: "memory")
#define CP_WAIT0() asm volatile("cp.async.wait_group 0;" ::: "memory")
#define LDSM_X4(r0, r1, r2, r3, addr)                                        \
    asm volatile("ldmatrix.sync.aligned.m8n8.x4.shared.b16 {%0,%1,%2,%3}, [%4];" \
                 : "=r"(r0), "=r"(r1), "=r"(r2), "=r"(r3) : "r"(addr))

__device__ __forceinline__ void mma_fp16(float* d, const uint32_t* a, const uint32_t* b) {
    asm volatile(
        "mma.sync.aligned.m16n8k16.row.col.f32.f16.f16.f32 "
        "{%0,%1,%2,%3}, {%4,%5,%6,%7}, {%8,%9}, {%0,%1,%2,%3};"
        : "+f"(d[0]), "+f"(d[1]), "+f"(d[2]), "+f"(d[3])
        : "r"(a[0]), "r"(a[1]), "r"(a[2]), "r"(a[3]), "r"(b[0]), "r"(b[1]));
}

// two-smallest update / merge (exact)
__device__ __forceinline__ void ts_upd(float& m1, float& m2, float v) {
    if (v < m1) { m2 = m1; m1 = v; } else if (v < m2) { m2 = v; }
}
__device__ __forceinline__ float2 ts_merge2(float2 a, float2 b) {
    float2 r;
    r.x = fminf(a.x, b.x);
    r.y = fminf(fmaxf(a.x, b.x), fminf(a.y, b.y));
    return r;
}

// ---------------- fused transpose_in + prep + weight packing + flag reset ----------------
__global__ void __launch_bounds__(256) fused_prep(const float* __restrict__ x,
                          const float* __restrict__ w1, const float* __restrict__ wg,
                          const float* __restrict__ w2,
                          const float* __restrict__ b1, const float* __restrict__ g1,
                          const float* __restrict__ be1, const float* __restrict__ m1,
                          const float* __restrict__ v1,
                          const float* __restrict__ bg, const float* __restrict__ gg,
                          const float* __restrict__ beg, const float* __restrict__ mg,
                          const float* __restrict__ vg,
                          const float* __restrict__ b2, const float* __restrict__ g2,
                          const float* __restrict__ be2, const float* __restrict__ m2,
                          const float* __restrict__ v2) {
    int blk = blockIdx.x;
    if (blk < 6272) {
        __shared__ float t[32][33];
        int tx = threadIdx.x & 31, ty = threadIdx.x >> 5;
        int s0 = (blk % 98) * 32, c0 = ((blk / 98) & 7) * 32, b = blk / 784;
        const float* xp = x + ((size_t)b * DIM + c0) * SPX + s0;
        for (int i = ty; i < 32; i += 8) t[i][tx] = xp[(size_t)i * SPX + tx];
        __syncthreads();
        __half* op = g_xTh + ((size_t)(b * SPX + s0)) * DIM + c0;
        for (int i = ty; i < 32; i += 8)
            op[(size_t)i * DIM + tx] = __float2half_rn(t[tx][i]);
        return;
    }
    if (blk < 6720) {
        int pb = blk - 6272;
        int idx = pb * 256 + threadIdx.x;  // float4 index
        const float4* src;
        __half* dst;
        if (pb < 64) { src = (const float4*)w1; dst = g_w1h; }
        else if (pb < 320) { src = (const float4*)wg; dst = g_wgh; idx -= 16384; }
        else { src = (const float4*)w2; dst = g_w2h; idx -= 81920; }
        float4 f = src[idx];
        *(__half2*)(dst + (size_t)idx * 4) = __floats2half2_rn(f.x, f.y);
        *(__half2*)(dst + (size_t)idx * 4 + 2) = __floats2half2_rn(f.z, f.w);
        return;
    }
    int i = threadIdx.x;
    {
        float s = g1[i] / sqrtf(v1[i] + 1e-5f);
        g_sc1[i] = s; g_sh1[i] = (b1[i] - m1[i]) * s + be1[i];
        float s2 = g2[i] / sqrtf(v2[i] + 1e-5f);
        g_sc2[i] = s2; g_sh2[i] = (b2[i] - m2[i]) * s2 + be2[i];
    }
#pragma unroll
    for (int r = 0; r < 2; r++) {
        int j = i + r * 256;
        float sg = gg[j] / sqrtf(vg[j] + 1e-5f);
        g_scg[j] = sg; g_shg[j] = (bg[j] - mg[j]) * sg + beg[j];
    }
    for (int j = i; j < 1176; j += 256) g_flags[j] = 0;
    if (i == 0) g_counter = 0;
}

// ---------------- MRConv4d pass 1: col (full) + row (halves), 4-way tracker ILP ----------------
__global__ void __launch_bounds__(256) minpass_kernel() {
    int b = blockIdx.y, c = threadIdx.x;
    float m1[4], m2[4];
#pragma unroll
    for (int q = 0; q < 4; q++) { m1[q] = 1e30f; m2[q] = 1e30f; }
    if (blockIdx.z == 0) {
        int x = blockIdx.x;
        const __half* base = g_cath + ((size_t)(b * SPX + x)) * DIM2 + c;
        for (int j = 0; j < 14; j++) {
            float v[4];
#pragma unroll
            for (int q = 0; q < 4; q++)
                v[q] = __half2float(__ldg(&base[(size_t)((4 * j + q) * 56) * DIM2]));
#pragma unroll
            for (int q = 0; q < 4; q++) ts_upd(m1[q], m2[q], v[q]);
        }
        float2 e = ts_merge2(make_float2(m1[0], m2[0]), make_float2(m1[2], m2[2]));
        float2 o = ts_merge2(make_float2(m1[1], m2[1]), make_float2(m1[3], m2[3]));
        size_t ofs = (((size_t)(b * 56 + x)) * 2) * DIM + c;
        g_cmm[ofs] = e;
        g_cmm[ofs + DIM] = o;
    } else {
        int y = blockIdx.x, h = blockIdx.z - 1;
        const __half* base = g_cath + ((size_t)(b * SPX + y * 56 + h * 28)) * DIM2 + c;
        for (int j = 0; j < 7; j++) {
            float v[4];
#pragma unroll
            for (int q = 0; q < 4; q++)
                v[q] = __half2float(__ldg(&base[(size_t)(4 * j + q) * DIM2]));
#pragma unroll
            for (int q = 0; q < 4; q++) ts_upd(m1[q], m2[q], v[q]);
        }
        float2 e = ts_merge2(make_float2(m1[0], m2[0]), make_float2(m1[2], m2[2]));
        float2 o = ts_merge2(make_float2(m1[1], m2[1]), make_float2(m1[3], m2[3]));
        size_t ofs = (((size_t)(b * 56 + y) * 2 + h) * 2) * DIM + c;
        g_rmp[ofs] = e;
        g_rmp[ofs + DIM] = o;
    }
}

// ---------------- MRConv4d pass 2: combine -> xj (R14: front-batched, MLP~28) ----------------
__global__ void __launch_bounds__(256) combine_kernel() {
    int y = blockIdx.x, b = blockIdx.y, xq = blockIdx.z, c = threadIdx.x;
    float2 r[2];
    {
        size_t o0 = (((size_t)(b * 56 + y) * 2 + 0) * 2) * DIM + c;
        size_t o1 = o0 + 2 * DIM;
#pragma unroll
        for (int p = 0; p < 2; p++)
            r[p] = ts_merge2(g_rmp[o0 + p * DIM], g_rmp[o1 + p * DIM]);
    }
    int py = y & 1;
    const int x0 = xq * 14;
    const __half* hb = g_cath + ((size_t)(b * SPX + y * 56 + x0)) * DIM2 + c;
    __half* ob = g_cath + ((size_t)(b * SPX + y * 56 + x0)) * DIM2 + DIM + c;
    const float2* cmb = g_cmm + (((size_t)(b * 56 + x0)) * 2 + py) * DIM + c;

    __half hv[14];
    float2 cmv[14];
#pragma unroll
    for (int i = 0; i < 14; i++) hv[i] = __ldg(&hb[(size_t)i * DIM2]);
#pragma unroll
    for (int i = 0; i < 14; i++) cmv[i] = __ldg(&cmb[(size_t)i * 2 * DIM]);

#pragma unroll
    for (int i = 0; i < 14; i++) {
        float v = __half2float(hv[i]);
        float ec = (v == cmv[i].x) ? cmv[i].y : cmv[i].x;
        float2 rr = r[i & 1];
        float er = (v == rr.x) ? rr.y : rr.x;
        ob[(size_t)i * DIM2] = __float2half_rn(fmaxf(0.0f, v - fminf(ec, er)));
    }
}

// ---------------- GEMM tile body (device function, fully templated) ----------------
// CTA 128x128, 8 warps (2m x 4n) of 64x32, BK=64, 2-stage cp.async.
// MODE 0: BN -> fp16, row stride 512
// MODE 1: BN + exact GELU -> fp16, row stride 512
// MODE 2: split-K fc2. bz = k-half. 0: raw fp32 partial + flag; 1: wait, add,
//         BN + residual + transposed fp32 store.
#define GSMEM 66560
template <int MODE, int KSTRIDE, int KLEN>
__device__ __forceinline__ void gemm_body(
    int bx, int by, int bz, char* smem,
    const __half* __restrict__ Ag, const __half* __restrict__ Wg,
    void* __restrict__ dstv, const float* __restrict__ xres,
    float* __restrict__ partial, int* __restrict__ flags,
    const float* __restrict__ scale, const float* __restrict__ shift) {
    __shared__ float s_scale[128], s_shift[128];
    const int tid = threadIdx.x, lane = tid & 31, wid = tid >> 5;
    const int warp_m = wid >> 2, warp_n = wid & 3;
    const int r0 = bx * 128, n0 = by * 128;
    const int koff = (MODE == 2) ? bz * KLEN : 0;
    const uint32_t sb = smem_u32(smem);
    if (tid < 128) { s_scale[tid] = scale[n0 + tid]; s_shift[tid] = shift[n0 + tid]; }

    uint32_t loff[4];
    size_t aoff[4], boff[4];
#pragma unroll
    for (int i = 0; i < 4; i++) {
        int idx = tid + i * 256;
        int row = idx >> 3, c = idx & 7;
        loff[i] = row * 128 + ((c ^ (row & 7)) << 4);
        aoff[i] = (size_t)(r0 + row) * KSTRIDE + koff + c * 8;
        boff[i] = (size_t)(n0 + row) * KSTRIDE + koff + c * 8;
    }

    const int rowA[4] = {warp_m * 64 + 0 * 16 + (lane & 7) + ((lane >> 3) & 1) * 8,
                         warp_m * 64 + 1 * 16 + (lane & 7) + ((lane >> 3) & 1) * 8,
                         warp_m * 64 + 2 * 16 + (lane & 7) + ((lane >> 3) & 1) * 8,
                         warp_m * 64 + 3 * 16 + (lane & 7) + ((lane >> 3) & 1) * 8};
    const int kcA = lane >> 4;
    const int rowB[2] = {warp_n * 32 + 0 * 16 + (lane & 7) + ((lane >> 4) & 1) * 8,
                         warp_n * 32 + 1 * 16 + (lane & 7) + ((lane >> 4) & 1) * 8};
    const int kcB = (lane >> 3) & 1;

    float acc[4][4][4];
#pragma unroll
    for (int a = 0; a < 4; a++)
#pragma unroll
        for (int b = 0; b < 4; b++)
#pragma unroll
            for (int i = 0; i < 4; i++) acc[a][b][i] = 0.0f;

    constexpr int NS = KLEN >> 6;

#pragma unroll
    for (int i = 0; i < 4; i++) {
        CP_ASYNC16(sb + loff[i], Ag + aoff[i]);
        CP_ASYNC16(sb + 16384 + loff[i], Wg + boff[i]);
    }
    CP_COMMIT();

#pragma unroll
    for (int s = 0; s < NS; s++) {
        const uint32_t aBase = sb + (s & 1) * 32768;
        const uint32_t bBase = aBase + 16384;
        if (s + 1 < NS) {
            const uint32_t nb = sb + ((s + 1) & 1) * 32768;
            const size_t kadd = (size_t)(s + 1) * 64;
#pragma unroll
            for (int i = 0; i < 4; i++) {
                CP_ASYNC16(nb + loff[i], Ag + aoff[i] + kadd);
                CP_ASYNC16(nb + 16384 + loff[i], Wg + boff[i] + kadd);
            }
            CP_COMMIT();
            CP_WAIT1();
        } else {
            CP_WAIT0();
        }
        __syncthreads();

#pragma unroll
        for (int kk = 0; kk < 4; kk++) {
            uint32_t af[4][4];
#pragma unroll
            for (int mf = 0; mf < 4; mf++) {
                uint32_t addr = aBase + rowA[mf] * 128 +
                                (((kk * 2 + kcA) ^ (rowA[mf] & 7)) << 4);
                LDSM_X4(af[mf][0], af[mf][1], af[mf][2], af[mf][3], addr);
            }
            uint32_t bf[2][4];
#pragma unroll
            for (int nb2 = 0; nb2 < 2; nb2++) {
                uint32_t addr = bBase + rowB[nb2] * 128 +
                                (((kk * 2 + kcB) ^ (rowB[nb2] & 7)) << 4);
                LDSM_X4(bf[nb2][0], bf[nb2][1], bf[nb2][2], bf[nb2][3], addr);
            }
#pragma unroll
            for (int mf = 0; mf < 4; mf++)
#pragma unroll
                for (int nf = 0; nf < 4; nf++)
                    mma_fp16(acc[mf][nf], af[mf], &bf[nf >> 1][(nf & 1) * 2]);
        }
        __syncthreads();
    }

    // ---------------- epilogue ----------------
    if (MODE == 2) {
        const int tileid = bx + by * 196;
        if (bz == 0) {
#pragma unroll
            for (int mf = 0; mf < 4; mf++)
#pragma unroll
                for (int nf = 0; nf < 4; nf++)
#pragma unroll
                    for (int half = 0; half < 2; half++) {
                        int grow = r0 + warp_m * 64 + mf * 16 + (lane >> 2) + half * 8;
                        int lcol = warp_n * 32 + nf * 8 + (lane & 3) * 2;
                        *(float2*)(partial + (size_t)grow * 256 + n0 + lcol) =
                            make_float2(acc[mf][nf][half * 2 + 0], acc[mf][nf][half * 2 + 1]);
                    }
            __threadfence();
            __syncthreads();
            if (tid == 0) atomicExch(&flags[tileid], 1);
            return;
        }
        if (tid == 0) {
            while (atomicAdd(&flags[tileid], 0) == 0) {}
        }
        __syncthreads();
        __threadfence();
#pragma unroll
        for (int mf = 0; mf < 4; mf++)
#pragma unroll
            for (int nf = 0; nf < 4; nf++)
#pragma unroll
                for (int half = 0; half < 2; half++) {
                    int grow = r0 + warp_m * 64 + mf * 16 + (lane >> 2) + half * 8;
                    int lcol = warp_n * 32 + nf * 8 + (lane & 3) * 2;
                    float2 p = *(const float2*)(partial + (size_t)grow * 256 + n0 + lcol);
                    acc[mf][nf][half * 2 + 0] += p.x;
                    acc[mf][nf][half * 2 + 1] += p.y;
                }
        __syncthreads();
        float* stg = (float*)smem;  // 128 x 129 fp32 staging
#pragma unroll
        for (int mf = 0; mf < 4; mf++)
#pragma unroll
            for (int nf = 0; nf < 4; nf++)
#pragma unroll
                for (int half = 0; half < 2; half++) {
                    int rl = warp_m * 64 + mf * 16 + (lane >> 2) + half * 8;
                    int cl = warp_n * 32 + nf * 8 + (lane & 3) * 2;
                    stg[rl * 129 + cl] = fmaf(acc[mf][nf][half * 2 + 0], s_scale[cl], s_shift[cl]);
                    stg[rl * 129 + cl + 1] =
                        fmaf(acc[mf][nf][half * 2 + 1], s_scale[cl + 1], s_shift[cl + 1]);
                }
        __syncthreads();
        float* out = (float*)dstv;
#pragma unroll
        for (int cc = 0; cc < 16; cc++) {
            int c = wid * 16 + cc;
#pragma unroll
            for (int j = 0; j < 4; j++) {
                int i = lane + 32 * j;
                int r = r0 + i;
                int b = r / SPX;
                size_t o = ((size_t)(b * DIM + n0 + c)) * SPX + (r - b * SPX);
                out[o] = stg[i * 129 + c] + xres[o];
            }
        }
        return;
    }

    const int mw = r0 + warp_m * 64;
    const int nw = warp_n * 32;
    __half* dp_base = (__half*)dstv;
#pragma unroll
    for (int mf = 0; mf < 4; mf++) {
#pragma unroll
        for (int nf = 0; nf < 4; nf++) {
#pragma unroll
            for (int half = 0; half < 2; half++) {
                int grow = mw + mf * 16 + (lane >> 2) + half * 8;
                int lcol = nw + nf * 8 + (lane & 3) * 2;
                float v0 = fmaf(acc[mf][nf][half * 2 + 0], s_scale[lcol], s_shift[lcol]);
                float v1 = fmaf(acc[mf][nf][half * 2 + 1], s_scale[lcol + 1], s_shift[lcol + 1]);
                if (MODE == 1) {
                    v0 = 0.5f * v0 * (1.0f + erff(v0 * 0.70710678118654752f));
                    v1 = 0.5f * v1 * (1.0f + erff(v1 * 0.70710678118654752f));
                }
                __half2 hp;
                hp.x = __float2half_rn(v0);
                hp.y = __float2half_rn(v1);
                *(__half2*)(dp_base + (size_t)grow * DIM2 + n0 + lcol) = hp;
            }
        }
    }
}

// ---------------- fc1 kernel (standalone) ----------------
__global__ void __launch_bounds__(256, 2)
fc1_kernel(const __half* __restrict__ Ag, const __half* __restrict__ Wg,
           void* __restrict__ dstv, const float* __restrict__ scale,
           const float* __restrict__ shift) {
    extern __shared__ __align__(1024) char smem[];
    gemm_body<0, 256, 256>(blockIdx.x, blockIdx.y, 0, smem, Ag, Wg, dstv,
                           nullptr, nullptr, nullptr, scale, shift);
}

// ---------------- persistent gemm2 + fc2 with work-stealing scheduler ----------------
// 296 CTAs loop on a global counter. Tile order:
//   t in [0,784):      gemm2 tile (r0i = t%196, n0i = t/196) -> gh, publish flags[t]
//   t in [784,1176):   fc2 k-half 0 tile u = t-784 (waits its 2 gemm2 producers)
//   t in [1176,1568):  fc2 k-half 1 tile u = t-1176 (waits producers; partial via flags[784+u])
__global__ void __launch_bounds__(256, 2)
persist_g2fc2(const __half* __restrict__ cath, const __half* __restrict__ wgh,
              __half* __restrict__ gh, const __half* __restrict__ w2h,
              float* __restrict__ out, const float* __restrict__ xres,
              float* __restrict__ partial, int* __restrict__ flags,
              const float* __restrict__ scg, const float* __restrict__ shg,
              const float* __restrict__ sc2, const float* __restrict__ sh2) {
    extern __shared__ __align__(1024) char smem[];
    __shared__ int s_tile;
    for (;;) {
        if (threadIdx.x == 0) s_tile = atomicAdd(&g_counter, 1);
        __syncthreads();
        const int t = s_tile;
        if (t >= 1568) return;
        if (t < 784) {
            int r0i = t % 196, n0i = t / 196;
            gemm_body<1, 512, 512>(r0i, n0i, 0, smem, cath, wgh, gh,
                                   nullptr, nullptr, nullptr, scg, shg);
            __threadfence();
            __syncthreads();
            if (threadIdx.x == 0) atomicExch(&flags[t], 1);
        } else {
            int u = t - 784;
            int z = (u >= 392) ? 1 : 0;
            if (z) u -= 392;
            int r0i = u % 196, n0i = u / 196;
            if (threadIdx.x == 0) {
                int p0 = r0i + 392 * z;      // gemm2 producer tiles for gh cols [256z, 256z+256)
                int p1 = p0 + 196;
                while (atomicAdd(&flags[p0], 0) == 0) {}
                while (atomicAdd(&flags[p1], 0) == 0) {}
            }
            __syncthreads();
            __threadfence();
            gemm_body<2, 512, 256>(r0i, n0i, z, smem, gh, w2h, out,
                                   xres, partial, flags + 784, sc2, sh2);
        }
        __syncthreads();  // protect s_tile and smem reuse across iterations
    }
}

// ---------------------------------------------------------------------------
extern "C" void kernel_launch(void* const* d_in, const int* in_sizes, int n_in,
                              void* d_out, int out_size) {
    const float* x   = (const float*)d_in[0];
    const float* w1  = (const float*)d_in[1];
    const float* b1  = (const float*)d_in[2];
    const float* g1  = (const float*)d_in[3];
    const float* be1 = (const float*)d_in[4];
    const float* m1  = (const float*)d_in[5];
    const float* v1  = (const float*)d_in[6];
    const float* wg  = (const float*)d_in[7];
    const float* bg  = (const float*)d_in[8];
    const float* gg  = (const float*)d_in[9];
    const float* beg = (const float*)d_in[10];
    const float* mg  = (const float*)d_in[11];
    const float* vg  = (const float*)d_in[12];
    const float* w2  = (const float*)d_in[13];
    const float* b2  = (const float*)d_in[14];
    const float* g2  = (const float*)d_in[15];
    const float* be2 = (const float*)d_in[16];
    const float* m2  = (const float*)d_in[17];
    const float* v2  = (const float*)d_in[18];

    __half *xTh, *cath, *gh, *w1h, *wgh, *w2h;
    float *part, *sc1, *sh1, *scg, *shg, *sc2, *sh2;
    int* flags;
    cudaGetSymbolAddress((void**)&xTh, g_xTh);
    cudaGetSymbolAddress((void**)&cath, g_cath);
    cudaGetSymbolAddress((void**)&gh, g_gh);
    cudaGetSymbolAddress((void**)&part, g_part);
    cudaGetSymbolAddress((void**)&w1h, g_w1h);
    cudaGetSymbolAddress((void**)&wgh, g_wgh);
    cudaGetSymbolAddress((void**)&w2h, g_w2h);
    cudaGetSymbolAddress((void**)&sc1, g_sc1);
    cudaGetSymbolAddress((void**)&sh1, g_sh1);
    cudaGetSymbolAddress((void**)&scg, g_scg);
    cudaGetSymbolAddress((void**)&shg, g_shg);
    cudaGetSymbolAddress((void**)&sc2, g_sc2);
    cudaGetSymbolAddress((void**)&sh2, g_sh2);
    cudaGetSymbolAddress((void**)&flags, g_flags);

    cudaFuncSetAttribute(fc1_kernel, cudaFuncAttributeMaxDynamicSharedMemorySize, GSMEM);
    cudaFuncSetAttribute(persist_g2fc2, cudaFuncAttributeMaxDynamicSharedMemorySize, GSMEM);

    // transpose + weight pack + BN fold + flag/counter reset
    fused_prep<<<6721, 256>>>(x, w1, wg, w2, b1, g1, be1, m1, v1,
                              bg, gg, beg, mg, vg, b2, g2, be2, m2, v2);

    // fc1: cat[:, 0:256] = fp16(BN(x @ w1^T))
    fc1_kernel<<<dim3(196, 2), 256, GSMEM>>>(xTh, w1h, cath, sc1, sh1);
    // MRConv4d -> cat[:, 256:512]
    minpass_kernel<<<dim3(56, 8, 3), 256>>>();
    combine_kernel<<<dim3(56, 8, 4), 256>>>();
    // persistent: g = fp16(GELU(BN(cat @ wg^T))); out = BN(g @ w2^T)^T + x
    persist_g2fc2<<<296, 256, GSMEM>>>(cath, wgh, gh, w2h, (float*)d_out, x,
                                       part, flags, scg, shg, sc2, sh2);
}